// round 1
// baseline (speedup 1.0000x reference)
#include <cuda_runtime.h>
#include <math.h>

// Problem constants
#define BATCH 2048
#define HID   512
#define IND   128
#define OUTD  128
#define SEQ   128

// --------------------------------------------------------------------------
// Device scratch (no cudaMalloc allowed)
// --------------------------------------------------------------------------
__device__ float g_x  [BATCH * IND];        // current input (y from prev step)
__device__ float g_hA [BATCH * HID];        // GRU state ping
__device__ float g_hB [BATCH * HID];        // GRU state pong
__device__ float g_grz[BATCH * 2 * HID];    // combined gi+gh+biases for r,z gates
__device__ float g_gin[BATCH * HID];        // gi_n + b_ih_n
__device__ float g_ghn[BATCH * HID];        // gh_n + b_hh_n

// --------------------------------------------------------------------------
// Kernel 1: gates GEMM.
//   For gate columns j in [0,1024) (r,z): grz[b,j] = x@w_ih^T + h@w_hh^T + b_ih + b_hh
//   For gate columns j in [1024,1536) (n): gin[b,h]=x@w_ih^T+b_ih ; ghn[b,h]=h@w_hh^T+b_hh
// Tiling: BM=64, BN=64, BK=16, 256 threads, 4x4 micro-tile per thread.
// --------------------------------------------------------------------------
__global__ __launch_bounds__(256) void gemm_gates(
    const float* __restrict__ x,   const float* __restrict__ h,
    const float* __restrict__ w_ih,const float* __restrict__ w_hh,
    const float* __restrict__ b_ih,const float* __restrict__ b_hh,
    float* __restrict__ grz, float* __restrict__ gin, float* __restrict__ ghn)
{
    __shared__ float As[16][64];
    __shared__ float Ws[16][64];

    const int t  = threadIdx.x;
    const int m0 = blockIdx.y * 64;
    const int n0 = blockIdx.x * 64;          // gate-column tile base (0..1472)
    const bool is_n_gate = (n0 >= 2 * HID);

    const int tx = t & 15, ty = t >> 4;
    const int tm = ty * 4, tn = tx * 4;

    const int lr = t >> 2;                   // 0..63 : row within tile
    const int lc = (t & 3) * 4;              // 0,4,8,12 : k offset

    float acc[4][4] = {};

    // ---------------- phase 1: input x (K = IND = 128), weights w_ih ----------------
    for (int k0 = 0; k0 < IND; k0 += 16) {
        float4 av = *reinterpret_cast<const float4*>(&x   [(m0 + lr) * IND + k0 + lc]);
        float4 wv = *reinterpret_cast<const float4*>(&w_ih[(n0 + lr) * IND + k0 + lc]);
        As[lc + 0][lr] = av.x; As[lc + 1][lr] = av.y; As[lc + 2][lr] = av.z; As[lc + 3][lr] = av.w;
        Ws[lc + 0][lr] = wv.x; Ws[lc + 1][lr] = wv.y; Ws[lc + 2][lr] = wv.z; Ws[lc + 3][lr] = wv.w;
        __syncthreads();
#pragma unroll
        for (int kk = 0; kk < 16; kk++) {
            float4 a = *reinterpret_cast<const float4*>(&As[kk][tm]);
            float4 b = *reinterpret_cast<const float4*>(&Ws[kk][tn]);
            float av_[4] = {a.x, a.y, a.z, a.w};
            float bv_[4] = {b.x, b.y, b.z, b.w};
#pragma unroll
            for (int i = 0; i < 4; i++)
#pragma unroll
                for (int j = 0; j < 4; j++)
                    acc[i][j] += av_[i] * bv_[j];
        }
        __syncthreads();
    }

    if (is_n_gate) {
        // store gi_n (+ b_ih) and restart accumulation for gh_n
#pragma unroll
        for (int i = 0; i < 4; i++) {
            const int m = m0 + tm + i;
#pragma unroll
            for (int j = 0; j < 4; j++) {
                const int n = n0 + tn + j;
                gin[m * HID + (n - 2 * HID)] = acc[i][j] + b_ih[n];
                acc[i][j] = 0.0f;
            }
        }
    }

    // ---------------- phase 2: state h (K = HID = 512), weights w_hh ----------------
    for (int k0 = 0; k0 < HID; k0 += 16) {
        float4 av = *reinterpret_cast<const float4*>(&h   [(m0 + lr) * HID + k0 + lc]);
        float4 wv = *reinterpret_cast<const float4*>(&w_hh[(n0 + lr) * HID + k0 + lc]);
        As[lc + 0][lr] = av.x; As[lc + 1][lr] = av.y; As[lc + 2][lr] = av.z; As[lc + 3][lr] = av.w;
        Ws[lc + 0][lr] = wv.x; Ws[lc + 1][lr] = wv.y; Ws[lc + 2][lr] = wv.z; Ws[lc + 3][lr] = wv.w;
        __syncthreads();
#pragma unroll
        for (int kk = 0; kk < 16; kk++) {
            float4 a = *reinterpret_cast<const float4*>(&As[kk][tm]);
            float4 b = *reinterpret_cast<const float4*>(&Ws[kk][tn]);
            float av_[4] = {a.x, a.y, a.z, a.w};
            float bv_[4] = {b.x, b.y, b.z, b.w};
#pragma unroll
            for (int i = 0; i < 4; i++)
#pragma unroll
                for (int j = 0; j < 4; j++)
                    acc[i][j] += av_[i] * bv_[j];
        }
        __syncthreads();
    }

    if (is_n_gate) {
#pragma unroll
        for (int i = 0; i < 4; i++) {
            const int m = m0 + tm + i;
#pragma unroll
            for (int j = 0; j < 4; j++) {
                const int n = n0 + tn + j;
                ghn[m * HID + (n - 2 * HID)] = acc[i][j] + b_hh[n];
            }
        }
    } else {
#pragma unroll
        for (int i = 0; i < 4; i++) {
            const int m = m0 + tm + i;
#pragma unroll
            for (int j = 0; j < 4; j++) {
                const int n = n0 + tn + j;
                grz[m * (2 * HID) + n] = acc[i][j] + b_ih[n] + b_hh[n];
            }
        }
    }
}

// --------------------------------------------------------------------------
// Kernel 2: elementwise GRU gate math.
//   r = sig(grz[:, h]); z = sig(grz[:, 512+h]); n = tanh(gin + r*ghn)
//   h_new = (1-z)*n + z*h_old
// --------------------------------------------------------------------------
__global__ __launch_bounds__(256) void gru_gates(
    const float* __restrict__ grz, const float* __restrict__ gin,
    const float* __restrict__ ghn, const float* __restrict__ h_old,
    float* __restrict__ h_new)
{
    const int i = blockIdx.x * 256 + threadIdx.x;   // i in [0, BATCH*HID)
    const int b = i / HID;
    const int hh = i - b * HID;
    const float r = 1.0f / (1.0f + expf(-grz[b * (2 * HID) + hh]));
    const float z = 1.0f / (1.0f + expf(-grz[b * (2 * HID) + HID + hh]));
    const float n = tanhf(gin[i] + r * ghn[i]);
    h_new[i] = (1.0f - z) * n + z * h_old[i];
}

// --------------------------------------------------------------------------
// Kernel 3: fc GEMM. y = h_new @ fc_w^T + fc_b  (M=2048, N=128, K=512)
// Writes y to g_x (next step's input) and to out[b, SEQ-1-t, :].
// Tiling: BM=64, BN=32, BK=16, 256 threads, 4x2 micro-tile.
// --------------------------------------------------------------------------
__global__ __launch_bounds__(256) void fc_kernel(
    const float* __restrict__ hnew, const float* __restrict__ fc_w,
    const float* __restrict__ fc_b, float* __restrict__ xnext,
    float* __restrict__ out, int row_off /* = (SEQ-1-t)*OUTD */)
{
    __shared__ float As[16][64];
    __shared__ float Ws[16][32];

    const int t  = threadIdx.x;
    const int m0 = blockIdx.y * 64;
    const int n0 = blockIdx.x * 32;

    const int tx = t & 15, ty = t >> 4;
    const int tm = ty * 4, tn = tx * 2;

    const int lr = t >> 2;               // 0..63
    const int lc = (t & 3) * 4;          // 0,4,8,12
    const int wr = t >> 3;               // 0..31
    const int wc = (t & 7) * 2;          // 0..14

    float acc[4][2] = {};

    for (int k0 = 0; k0 < HID; k0 += 16) {
        float4 av = *reinterpret_cast<const float4*>(&hnew[(m0 + lr) * HID + k0 + lc]);
        As[lc + 0][lr] = av.x; As[lc + 1][lr] = av.y; As[lc + 2][lr] = av.z; As[lc + 3][lr] = av.w;
        float2 wv = *reinterpret_cast<const float2*>(&fc_w[(n0 + wr) * HID + k0 + wc]);
        Ws[wc + 0][wr] = wv.x; Ws[wc + 1][wr] = wv.y;
        __syncthreads();
#pragma unroll
        for (int kk = 0; kk < 16; kk++) {
            float4 a = *reinterpret_cast<const float4*>(&As[kk][tm]);
            float2 b = *reinterpret_cast<const float2*>(&Ws[kk][tn]);
            float av_[4] = {a.x, a.y, a.z, a.w};
            float bv_[2] = {b.x, b.y};
#pragma unroll
            for (int i = 0; i < 4; i++)
#pragma unroll
                for (int j = 0; j < 2; j++)
                    acc[i][j] += av_[i] * bv_[j];
        }
        __syncthreads();
    }

#pragma unroll
    for (int i = 0; i < 4; i++) {
        const int m = m0 + tm + i;
#pragma unroll
        for (int j = 0; j < 2; j++) {
            const int n = n0 + tn + j;
            const float y = acc[i][j] + fc_b[n];
            xnext[m * IND + n] = y;
            out[m * SEQ * OUTD + row_off + n] = y;
        }
    }
}

// --------------------------------------------------------------------------
// Launch: 128 sequential steps, 3 kernels each, graph-capturable.
// --------------------------------------------------------------------------
extern "C" void kernel_launch(void* const* d_in, const int* in_sizes, int n_in,
                              void* d_out, int out_size)
{
    const float* hidden = (const float*)d_in[0];
    const float* w_ih   = (const float*)d_in[1];
    const float* w_hh   = (const float*)d_in[2];
    const float* b_ih   = (const float*)d_in[3];
    const float* b_hh   = (const float*)d_in[4];
    const float* fc_w   = (const float*)d_in[5];
    const float* fc_b   = (const float*)d_in[6];
    float* out = (float*)d_out;

    float *px, *phA, *phB, *pgrz, *pgin, *pghn;
    cudaGetSymbolAddress((void**)&px,   g_x);
    cudaGetSymbolAddress((void**)&phA,  g_hA);
    cudaGetSymbolAddress((void**)&phB,  g_hB);
    cudaGetSymbolAddress((void**)&pgrz, g_grz);
    cudaGetSymbolAddress((void**)&pgin, g_gin);
    cudaGetSymbolAddress((void**)&pghn, g_ghn);

    // h0 = hidden[0]; x0 = 0
    cudaMemcpyAsync(phA, hidden, (size_t)BATCH * HID * sizeof(float),
                    cudaMemcpyDeviceToDevice);
    cudaMemsetAsync(px, 0, (size_t)BATCH * IND * sizeof(float));

    const dim3 gates_grid(3 * HID / 64, BATCH / 64);   // (24, 32)
    const dim3 fc_grid(OUTD / 32, BATCH / 64);         // (4, 32)

    for (int t = 0; t < SEQ; t++) {
        const float* hin = (t & 1) ? phB : phA;
        float*       hou = (t & 1) ? phA : phB;

        gemm_gates<<<gates_grid, 256>>>(px, hin, w_ih, w_hh, b_ih, b_hh,
                                        pgrz, pgin, pghn);
        gru_gates<<<(BATCH * HID) / 256, 256>>>(pgrz, pgin, pghn, hin, hou);
        fc_kernel<<<fc_grid, 256>>>(hou, fc_w, fc_b, px, out,
                                    (SEQ - 1 - t) * OUTD);
    }
}

// round 3
// speedup vs baseline: 1.8920x; 1.8920x over previous
#include <cuda_runtime.h>
#include <cuda_bf16.h>
#include <cstdint>
#include <math.h>

// Problem constants
#define BATCH 2048
#define HID   512
#define IND   128
#define OUTD  128
#define SEQ   128

// Split-bf16 extended-K geometry
#define KBASE 640                  // IND + HID
#define KEXT  1920                 // 3 * KBASE : parts (hi | hi | lo) vs W (hi | lo | hi)
#define NGATE 2048                 // 4 gates (r,z,i_n,h_n) * 512 units, unit-interleaved
#define FCK   1536                 // 3 * HID for fc split

// --------------------------------------------------------------------------
// Device scratch
// --------------------------------------------------------------------------
__device__ __nv_bfloat16 g_W[NGATE * KEXT];          // gates weights, split
__device__ __nv_bfloat16 g_fcW[OUTD * FCK];          // fc weights, split
__device__ __nv_bfloat16 g_act[2][BATCH * KEXT];     // activations ping/pong
__device__ float         g_bias[NGATE];

// --------------------------------------------------------------------------
// Helpers
// --------------------------------------------------------------------------
__device__ __forceinline__ uint32_t smem_u32(const void* p) {
    uint32_t a;
    asm("{ .reg .u64 t; cvta.to.shared.u64 t, %1; cvt.u32.u64 %0, t; }"
        : "=r"(a) : "l"(p));
    return a;
}
#define CP16(dst, src) \
    asm volatile("cp.async.cg.shared.global [%0], [%1], 16;" :: "r"(dst), "l"(src))
#define CP_COMMIT()  asm volatile("cp.async.commit_group;")
#define CP_WAIT1()   asm volatile("cp.async.wait_group 1;")
#define CP_WAIT0()   asm volatile("cp.async.wait_group 0;")

__device__ __forceinline__ void ldsm_x4(uint32_t* r, uint32_t addr) {
    asm volatile("ldmatrix.sync.aligned.m8n8.x4.shared.b16 {%0,%1,%2,%3}, [%4];"
        : "=r"(r[0]), "=r"(r[1]), "=r"(r[2]), "=r"(r[3]) : "r"(addr));
}
__device__ __forceinline__ void mma16816(float* d, const uint32_t* a, const uint32_t* b) {
    asm volatile(
        "mma.sync.aligned.m16n8k16.row.col.f32.bf16.bf16.f32 "
        "{%0,%1,%2,%3}, {%4,%5,%6,%7}, {%8,%9}, {%0,%1,%2,%3};"
        : "+f"(d[0]), "+f"(d[1]), "+f"(d[2]), "+f"(d[3])
        : "r"(a[0]), "r"(a[1]), "r"(a[2]), "r"(a[3]), "r"(b[0]), "r"(b[1]));
}
__device__ __forceinline__ float sigmoidf_(float v) { return 1.0f / (1.0f + expf(-v)); }

// --------------------------------------------------------------------------
// Prep kernels
// --------------------------------------------------------------------------
__global__ __launch_bounds__(256) void prep_weights(
    const float* __restrict__ w_ih, const float* __restrict__ w_hh,
    __nv_bfloat16* __restrict__ W)
{
    const int idx = blockIdx.x * 256 + threadIdx.x;   // over NGATE*KBASE
    if (idx >= NGATE * KBASE) return;
    const int n = idx / KBASE;
    const int k = idx - n * KBASE;
    const int g = n & 3;            // 0=r,1=z,2=i_n,3=h_n
    const int u = n >> 2;
    float w;
    if (k < IND) {
        w = (g == 3) ? 0.0f : w_ih[(g * HID + u) * IND + k];
    } else {
        const int kk = k - IND;
        if (g == 0)      w = w_hh[u * HID + kk];
        else if (g == 1) w = w_hh[(HID + u) * HID + kk];
        else if (g == 2) w = 0.0f;
        else             w = w_hh[(2 * HID + u) * HID + kk];
    }
    const __nv_bfloat16 hi = __float2bfloat16_rn(w);
    const __nv_bfloat16 lo = __float2bfloat16_rn(w - __bfloat162float(hi));
    W[(size_t)n * KEXT + k]             = hi;
    W[(size_t)n * KEXT + KBASE + k]     = lo;
    W[(size_t)n * KEXT + 2 * KBASE + k] = hi;
}

__global__ __launch_bounds__(256) void prep_fcw(
    const float* __restrict__ fc_w, __nv_bfloat16* __restrict__ fcW)
{
    const int idx = blockIdx.x * 256 + threadIdx.x;   // over OUTD*HID
    if (idx >= OUTD * HID) return;
    const int n = idx / HID;
    const int k = idx - n * HID;
    const float w = fc_w[idx];
    const __nv_bfloat16 hi = __float2bfloat16_rn(w);
    const __nv_bfloat16 lo = __float2bfloat16_rn(w - __bfloat162float(hi));
    fcW[(size_t)n * FCK + k]           = hi;
    fcW[(size_t)n * FCK + HID + k]     = lo;
    fcW[(size_t)n * FCK + 2 * HID + k] = hi;
}

__global__ __launch_bounds__(256) void prep_bias(
    const float* __restrict__ b_ih, const float* __restrict__ b_hh,
    float* __restrict__ bias)
{
    const int n = blockIdx.x * 256 + threadIdx.x;
    if (n >= NGATE) return;
    const int g = n & 3, u = n >> 2;
    float b;
    if (g == 0)      b = b_ih[u] + b_hh[u];
    else if (g == 1) b = b_ih[HID + u] + b_hh[HID + u];
    else if (g == 2) b = b_ih[2 * HID + u];
    else             b = b_hh[2 * HID + u];
    bias[n] = b;
}

__global__ __launch_bounds__(256) void prep_act0(
    const float* __restrict__ hidden, __nv_bfloat16* __restrict__ act)
{
    const int idx = blockIdx.x * 256 + threadIdx.x;   // over BATCH*KBASE
    if (idx >= BATCH * KBASE) return;
    const int m = idx / KBASE;
    const int c = idx - m * KBASE;
    __nv_bfloat16 hi, lo;
    if (c < IND) {
        hi = __float2bfloat16_rn(0.0f);
        lo = hi;
    } else {
        const float h = hidden[m * HID + (c - IND)];
        hi = __float2bfloat16_rn(h);
        lo = __float2bfloat16_rn(h - __bfloat162float(hi));
    }
    act[(size_t)m * KEXT + c]             = hi;
    act[(size_t)m * KEXT + KBASE + c]     = hi;
    act[(size_t)m * KEXT + 2 * KBASE + c] = lo;
}

// --------------------------------------------------------------------------
// Gates GEMM (warp MMA) + fused GRU epilogue
//   D[m,n] = act[m,:] . W[n,:]  (M=2048, N=2048, K=1920 bf16, fp32 acc)
//   CTA 128x128, BK=32, cp.async double buffer, 8 warps (2m x 4n), warp 64x32.
// --------------------------------------------------------------------------
#define GP     80                         // smem row pitch bytes (40 bf16)
#define G_AB   (128 * GP)                 // one A/B buffer: 10240 B
#define G_PIPE (4 * G_AB)                 // A0 A1 B0 B1 = 40960
#define G_SLABPITCH 34
#define G_SLAB (64 * G_SLABPITCH * 4)     // 8704 B per warp
#define G_SMEM (G_PIPE + 8 * G_SLAB)      // 110592 B
#define G_NIT  (KEXT / 32)                // 60

__global__ __launch_bounds__(256, 2)
void gates_kernel(const __nv_bfloat16* __restrict__ act,
                  const __nv_bfloat16* __restrict__ W,
                  const float* __restrict__ bias,
                  __nv_bfloat16* __restrict__ act_next)
{
    extern __shared__ char smem[];
    const uint32_t sb = smem_u32(smem);
    const int tid  = threadIdx.x;
    const int wid  = tid >> 5;
    const int lane = tid & 31;
    const int m0 = blockIdx.x * 128;
    const int n0 = blockIdx.y * 128;
    const int u0 = blockIdx.y * 32;

    const uint32_t sA0 = sb;
    const uint32_t sB0 = sb + 2 * G_AB;

    // loader mapping: 512 16B chunks per tile (128 rows x 4), 2 per thread
    const int r0c = tid >> 2,         ch0 = (tid & 3);
    const int r1c = (tid + 256) >> 2, ch1 = ((tid + 256) & 3);

    // fragment lane addressing
    const uint32_t aRow  = (uint32_t)(lane & 15);
    const uint32_t aKoff = (uint32_t)((lane >> 4) * 16);
    const uint32_t bRow  = (uint32_t)((lane & 7) + ((lane >> 4) << 3));
    const uint32_t bKoff = (uint32_t)(((lane >> 3) & 1) * 16);

    const int mW = (wid >> 2) * 64;
    const int nW = (wid & 3) * 32;

    float acc[4][4][4];
#pragma unroll
    for (int i = 0; i < 4; i++)
#pragma unroll
        for (int j = 0; j < 4; j++)
#pragma unroll
            for (int q = 0; q < 4; q++) acc[i][j][q] = 0.0f;

    // ---- prologue load (kc = 0, buf 0) ----
    {
        const int kb = 0;
        CP16(sA0 + r0c * GP + ch0 * 16, act + (size_t)(m0 + r0c) * KEXT + kb + ch0 * 8);
        CP16(sA0 + r1c * GP + ch1 * 16, act + (size_t)(m0 + r1c) * KEXT + kb + ch1 * 8);
        CP16(sB0 + r0c * GP + ch0 * 16, W   + (size_t)(n0 + r0c) * KEXT + kb + ch0 * 8);
        CP16(sB0 + r1c * GP + ch1 * 16, W   + (size_t)(n0 + r1c) * KEXT + kb + ch1 * 8);
        CP_COMMIT();
    }

    for (int kc = 0; kc < G_NIT; ++kc) {
        if (kc + 1 < G_NIT) {
            const int nb = (kc + 1) & 1;
            const uint32_t dA = sA0 + nb * G_AB;
            const uint32_t dB = sB0 + nb * G_AB;
            const int kb = (kc + 1) * 32;
            CP16(dA + r0c * GP + ch0 * 16, act + (size_t)(m0 + r0c) * KEXT + kb + ch0 * 8);
            CP16(dA + r1c * GP + ch1 * 16, act + (size_t)(m0 + r1c) * KEXT + kb + ch1 * 8);
            CP16(dB + r0c * GP + ch0 * 16, W   + (size_t)(n0 + r0c) * KEXT + kb + ch0 * 8);
            CP16(dB + r1c * GP + ch1 * 16, W   + (size_t)(n0 + r1c) * KEXT + kb + ch1 * 8);
            CP_COMMIT();
            CP_WAIT1();
        } else {
            CP_WAIT0();
        }
        __syncthreads();

        const int buf = kc & 1;
        const uint32_t cA = sA0 + buf * G_AB;
        const uint32_t cB = sB0 + buf * G_AB;
#pragma unroll
        for (int ks = 0; ks < 2; ++ks) {
            uint32_t a[4][4], b[2][4];
#pragma unroll
            for (int mt = 0; mt < 4; ++mt)
                ldsm_x4(a[mt], cA + (mW + mt * 16 + aRow) * GP + aKoff + ks * 32);
#pragma unroll
            for (int bj = 0; bj < 2; ++bj)
                ldsm_x4(b[bj], cB + (nW + bj * 16 + bRow) * GP + bKoff + ks * 32);
#pragma unroll
            for (int mt = 0; mt < 4; ++mt)
#pragma unroll
                for (int nt = 0; nt < 4; ++nt)
                    mma16816(acc[mt][nt], a[mt], &b[nt >> 1][(nt & 1) * 2]);
        }
        __syncthreads();
    }

    // ---- epilogue: per-warp slab -> GRU -> global (no cross-warp sync) ----
    float* slab = reinterpret_cast<float*>(smem + G_PIPE + wid * G_SLAB);
    const int gg = lane >> 2;
    const int t2 = (lane & 3) * 2;
#pragma unroll
    for (int mt = 0; mt < 4; ++mt)
#pragma unroll
        for (int nt = 0; nt < 4; ++nt) {
            const int r = mt * 16 + gg;
            const int c = nt * 8 + t2;
            slab[r * G_SLABPITCH + c]           = acc[mt][nt][0];
            slab[r * G_SLABPITCH + c + 1]       = acc[mt][nt][1];
            slab[(r + 8) * G_SLABPITCH + c]     = acc[mt][nt][2];
            slab[(r + 8) * G_SLABPITCH + c + 1] = acc[mt][nt][3];
        }
    __syncwarp();

#pragma unroll 4
    for (int i = 0; i < 16; ++i) {
        const int e   = lane + 32 * i;          // 0..511
        const int row = e >> 3;                 // 0..63
        const int uu  = e & 7;                  // unit within warp slab
        const int nb  = n0 + nW + uu * 4;
        const float pr = slab[row * G_SLABPITCH + uu * 4 + 0] + __ldg(&bias[nb + 0]);
        const float pz = slab[row * G_SLABPITCH + uu * 4 + 1] + __ldg(&bias[nb + 1]);
        const float pi = slab[row * G_SLABPITCH + uu * 4 + 2] + __ldg(&bias[nb + 2]);
        const float ph = slab[row * G_SLABPITCH + uu * 4 + 3] + __ldg(&bias[nb + 3]);
        const int m = m0 + mW + row;
        const size_t base = (size_t)m * KEXT;
        const int ug = u0 + (nW >> 2) + uu;
        const float ho = __bfloat162float(act[base + IND + ug]) +
                         __bfloat162float(act[base + 2 * KBASE + IND + ug]);
        const float r  = sigmoidf_(pr);
        const float z  = sigmoidf_(pz);
        const float nn = tanhf(pi + r * ph);
        const float hn = (1.0f - z) * nn + z * ho;
        const __nv_bfloat16 hi = __float2bfloat16_rn(hn);
        const __nv_bfloat16 lo = __float2bfloat16_rn(hn - __bfloat162float(hi));
        act_next[base + IND + ug]             = hi;
        act_next[base + KBASE + IND + ug]     = hi;
        act_next[base + 2 * KBASE + IND + ug] = lo;
    }
}

// --------------------------------------------------------------------------
// fc GEMM (warp MMA). y = h_new @ fc_w^T + fc_b (split-bf16, K=1536)
//   CTA 128x64, BK=32, 8 warps (4m x 2n), warp 32x32.
//   Writes y to out and hi/lo into x-part of act.
// --------------------------------------------------------------------------
#define F_A   (128 * GP)                 // 10240
#define F_B   (64 * GP)                  // 5120
#define F_PIPE (2 * F_A + 2 * F_B)       // 30720
#define F_SLAB (32 * G_SLABPITCH * 4)    // 4352
#define F_SMEM (F_PIPE + 8 * F_SLAB)     // 65536
#define F_NIT  (FCK / 32)                // 48

__global__ __launch_bounds__(256, 2)
void fc_kernel(const __nv_bfloat16* __restrict__ actH,
               const __nv_bfloat16* __restrict__ fcW,
               const float* __restrict__ fc_b,
               __nv_bfloat16* __restrict__ actX,
               float* __restrict__ out, int row_off)
{
    extern __shared__ char smem[];
    const uint32_t sb = smem_u32(smem);
    const int tid  = threadIdx.x;
    const int wid  = tid >> 5;
    const int lane = tid & 31;
    const int m0  = blockIdx.x * 128;
    const int n0f = blockIdx.y * 64;

    const uint32_t sA0 = sb;
    const uint32_t sB0 = sb + 2 * F_A;

    // A: 512 chunks -> 2/thread ; B: 256 chunks -> 1/thread
    const int r0c = tid >> 2,         ch0 = (tid & 3);
    const int r1c = (tid + 256) >> 2, ch1 = ((tid + 256) & 3);

    const uint32_t aRow  = (uint32_t)(lane & 15);
    const uint32_t aKoff = (uint32_t)((lane >> 4) * 16);
    const uint32_t bRow  = (uint32_t)((lane & 7) + ((lane >> 4) << 3));
    const uint32_t bKoff = (uint32_t)(((lane >> 3) & 1) * 16);

    const int mW = (wid >> 1) * 32;
    const int nW = (wid & 1) * 32;

    float acc[2][4][4];
#pragma unroll
    for (int i = 0; i < 2; i++)
#pragma unroll
        for (int j = 0; j < 4; j++)
#pragma unroll
            for (int q = 0; q < 4; q++) acc[i][j][q] = 0.0f;

    // A source address with part mapping: k' -> p*KBASE + IND + (k' & 511)
#define FC_ASRC(row, kprime) \
    (actH + (size_t)(m0 + (row)) * KEXT + ((kprime) >> 9) * KBASE + IND + ((kprime) & 511))

    {
        const int kb = 0;
        CP16(sA0 + r0c * GP + ch0 * 16, FC_ASRC(r0c, kb + ch0 * 8));
        CP16(sA0 + r1c * GP + ch1 * 16, FC_ASRC(r1c, kb + ch1 * 8));
        CP16(sB0 + r0c * GP + ch0 * 16, fcW + (size_t)(n0f + r0c) * FCK + kb + ch0 * 8);
        CP_COMMIT();
    }

    for (int kc = 0; kc < F_NIT; ++kc) {
        if (kc + 1 < F_NIT) {
            const int nb = (kc + 1) & 1;
            const uint32_t dA = sA0 + nb * F_A;
            const uint32_t dB = sB0 + nb * F_B;
            const int kb = (kc + 1) * 32;
            CP16(dA + r0c * GP + ch0 * 16, FC_ASRC(r0c, kb + ch0 * 8));
            CP16(dA + r1c * GP + ch1 * 16, FC_ASRC(r1c, kb + ch1 * 8));
            CP16(dB + r0c * GP + ch0 * 16, fcW + (size_t)(n0f + r0c) * FCK + kb + ch0 * 8);
            CP_COMMIT();
            CP_WAIT1();
        } else {
            CP_WAIT0();
        }
        __syncthreads();

        const int buf = kc & 1;
        const uint32_t cA = sA0 + buf * F_A;
        const uint32_t cB = sB0 + buf * F_B;
#pragma unroll
        for (int ks = 0; ks < 2; ++ks) {
            uint32_t a[2][4], b[2][4];
#pragma unroll
            for (int mt = 0; mt < 2; ++mt)
                ldsm_x4(a[mt], cA + (mW + mt * 16 + aRow) * GP + aKoff + ks * 32);
#pragma unroll
            for (int bj = 0; bj < 2; ++bj)
                ldsm_x4(b[bj], cB + (nW + bj * 16 + bRow) * GP + bKoff + ks * 32);
#pragma unroll
            for (int mt = 0; mt < 2; ++mt)
#pragma unroll
                for (int nt = 0; nt < 4; ++nt)
                    mma16816(acc[mt][nt], a[mt], &b[nt >> 1][(nt & 1) * 2]);
        }
        __syncthreads();
    }
#undef FC_ASRC

    // epilogue: per-warp slab -> y -> out + act x-part
    float* slab = reinterpret_cast<float*>(smem + F_PIPE + wid * F_SLAB);
    const int gg = lane >> 2;
    const int t2 = (lane & 3) * 2;
#pragma unroll
    for (int mt = 0; mt < 2; ++mt)
#pragma unroll
        for (int nt = 0; nt < 4; ++nt) {
            const int r = mt * 16 + gg;
            const int c = nt * 8 + t2;
            slab[r * G_SLABPITCH + c]           = acc[mt][nt][0];
            slab[r * G_SLABPITCH + c + 1]       = acc[mt][nt][1];
            slab[(r + 8) * G_SLABPITCH + c]     = acc[mt][nt][2];
            slab[(r + 8) * G_SLABPITCH + c + 1] = acc[mt][nt][3];
        }
    __syncwarp();

#pragma unroll 4
    for (int i = 0; i < 32; ++i) {
        const int e   = lane + 32 * i;          // 0..1023
        const int row = e >> 5;                 // 0..31
        const int c   = e & 31;
        const int n   = n0f + nW + c;
        const float y = slab[row * G_SLABPITCH + c] + __ldg(&fc_b[n]);
        const int m = m0 + mW + row;
        out[(size_t)m * SEQ * OUTD + row_off + n] = y;
        const __nv_bfloat16 hi = __float2bfloat16_rn(y);
        const __nv_bfloat16 lo = __float2bfloat16_rn(y - __bfloat162float(hi));
        const size_t base = (size_t)m * KEXT;
        actX[base + n]             = hi;
        actX[base + KBASE + n]     = hi;
        actX[base + 2 * KBASE + n] = lo;
    }
}

// --------------------------------------------------------------------------
// Launch
// --------------------------------------------------------------------------
extern "C" void kernel_launch(void* const* d_in, const int* in_sizes, int n_in,
                              void* d_out, int out_size)
{
    const float* hidden = (const float*)d_in[0];
    const float* w_ih   = (const float*)d_in[1];
    const float* w_hh   = (const float*)d_in[2];
    const float* b_ih   = (const float*)d_in[3];
    const float* b_hh   = (const float*)d_in[4];
    const float* fc_w   = (const float*)d_in[5];
    const float* fc_b   = (const float*)d_in[6];
    float* out = (float*)d_out;

    __nv_bfloat16 *pW, *pfcW, *pact;
    float* pbias;
    cudaGetSymbolAddress((void**)&pW,    g_W);
    cudaGetSymbolAddress((void**)&pfcW,  g_fcW);
    cudaGetSymbolAddress((void**)&pact,  g_act);
    cudaGetSymbolAddress((void**)&pbias, g_bias);
    __nv_bfloat16* pactA = pact;
    __nv_bfloat16* pactB = pact + (size_t)BATCH * KEXT;

    static int attr_set = 0;
    cudaFuncSetAttribute(gates_kernel, cudaFuncAttributeMaxDynamicSharedMemorySize, G_SMEM);
    cudaFuncSetAttribute(fc_kernel,    cudaFuncAttributeMaxDynamicSharedMemorySize, F_SMEM);
    (void)attr_set;

    prep_weights<<<(NGATE * KBASE + 255) / 256, 256>>>(w_ih, w_hh, pW);
    prep_fcw<<<(OUTD * HID + 255) / 256, 256>>>(fc_w, pfcW);
    prep_bias<<<(NGATE + 255) / 256, 256>>>(b_ih, b_hh, pbias);
    prep_act0<<<(BATCH * KBASE + 255) / 256, 256>>>(hidden, pactA);

    const dim3 gates_grid(BATCH / 128, NGATE / 128);   // (16, 16)
    const dim3 fc_grid(BATCH / 128, OUTD / 64);        // (16, 2)

    for (int t = 0; t < SEQ; t++) {
        __nv_bfloat16* cur = (t & 1) ? pactB : pactA;
        __nv_bfloat16* nxt = (t & 1) ? pactA : pactB;
        gates_kernel<<<gates_grid, 256, G_SMEM>>>(cur, pW, pbias, nxt);
        fc_kernel<<<fc_grid, 256, F_SMEM>>>(nxt, pfcW, fc_b, nxt, out,
                                            (SEQ - 1 - t) * OUTD);
    }
}

// round 4
// speedup vs baseline: 2.8644x; 1.5140x over previous
#include <cuda_runtime.h>
#include <cuda_bf16.h>
#include <cstdint>
#include <math.h>

// Problem constants
#define BATCH 2048
#define HID   512
#define IND   128
#define OUTD  128
#define SEQ   128

// Split-bf16 extended-K geometry (after fc-fold: K base = HID = 512)
#define KEXT  1536                 // 3 * 512 : act parts (hi | hi | lo) vs W (hi | lo | hi)
#define NGATE 2048                 // 4 gates (r,z,i_n,h_n) * 512 units, unit-interleaved

// --------------------------------------------------------------------------
// Device scratch
// --------------------------------------------------------------------------
__device__ __nv_bfloat16 g_W1[NGATE * KEXT];                  // steps >= 1
__device__ __nv_bfloat16 g_W0[NGATE * KEXT];                  // step 0 (x = 0)
__device__ __nv_bfloat16 g_fcW[OUTD * KEXT];                  // fc weights split
__device__ float         g_Wc[3 * HID * HID];                 // w_ih @ fc_w (fp32)
__device__ float         g_biasC[3 * HID];                    // w_ih @ fc_b + b_ih
__device__ float         g_bias1[NGATE];
__device__ float         g_bias0[NGATE];
// h history: slice t holds h_t as split triple [hi|hi|lo]; slices 0..SEQ.
__device__ __nv_bfloat16 g_hist[(size_t)(SEQ + 1) * BATCH * KEXT];   // ~812 MB

// --------------------------------------------------------------------------
// Helpers
// --------------------------------------------------------------------------
__device__ __forceinline__ uint32_t smem_u32(const void* p) {
    uint32_t a;
    asm("{ .reg .u64 t; cvta.to.shared.u64 t, %1; cvt.u32.u64 %0, t; }"
        : "=r"(a) : "l"(p));
    return a;
}
#define CP16(dst, src) \
    asm volatile("cp.async.cg.shared.global [%0], [%1], 16;" :: "r"(dst), "l"(src))
#define CP_COMMIT()  asm volatile("cp.async.commit_group;")
#define CP_WAIT1()   asm volatile("cp.async.wait_group 1;")
#define CP_WAIT0()   asm volatile("cp.async.wait_group 0;")

__device__ __forceinline__ void ldsm_x4(uint32_t* r, uint32_t addr) {
    asm volatile("ldmatrix.sync.aligned.m8n8.x4.shared.b16 {%0,%1,%2,%3}, [%4];"
        : "=r"(r[0]), "=r"(r[1]), "=r"(r[2]), "=r"(r[3]) : "r"(addr));
}
__device__ __forceinline__ void mma16816(float* d, const uint32_t* a, const uint32_t* b) {
    asm volatile(
        "mma.sync.aligned.m16n8k16.row.col.f32.bf16.bf16.f32 "
        "{%0,%1,%2,%3}, {%4,%5,%6,%7}, {%8,%9}, {%0,%1,%2,%3};"
        : "+f"(d[0]), "+f"(d[1]), "+f"(d[2]), "+f"(d[3])
        : "r"(a[0]), "r"(a[1]), "r"(a[2]), "r"(a[3]), "r"(b[0]), "r"(b[1]));
}
__device__ __forceinline__ float sigmoidf_(float v) { return 1.0f / (1.0f + expf(-v)); }

// --------------------------------------------------------------------------
// Prep 1: Wc = w_ih @ fc_w   (1536 x 512, K = 128), fp32 SIMT GEMM.
// --------------------------------------------------------------------------
__global__ __launch_bounds__(256) void prep_wc(
    const float* __restrict__ w_ih, const float* __restrict__ fc_w,
    float* __restrict__ Wc)
{
    __shared__ float As[16][64];   // [o][n]
    __shared__ float Bs[16][64];   // [o][k]
    const int t  = threadIdx.x;
    const int k0 = blockIdx.x * 64;
    const int n0 = blockIdx.y * 64;
    const int tx = t & 15, ty = t >> 4;
    const int tm = ty * 4, tn = tx * 4;
    float acc[4][4] = {};
    for (int o0 = 0; o0 < IND; o0 += 16) {
        {
            const int nn = t >> 2, o4 = (t & 3) * 4;
            const float4 v = *reinterpret_cast<const float4*>(
                &w_ih[(n0 + nn) * IND + o0 + o4]);
            As[o4 + 0][nn] = v.x; As[o4 + 1][nn] = v.y;
            As[o4 + 2][nn] = v.z; As[o4 + 3][nn] = v.w;
        }
        {
            const int oo = t >> 4, c4 = (t & 15) * 4;
            const float4 v = *reinterpret_cast<const float4*>(
                &fc_w[(o0 + oo) * HID + k0 + c4]);
            Bs[oo][c4 + 0] = v.x; Bs[oo][c4 + 1] = v.y;
            Bs[oo][c4 + 2] = v.z; Bs[oo][c4 + 3] = v.w;
        }
        __syncthreads();
#pragma unroll
        for (int kk = 0; kk < 16; kk++) {
            const float4 a = *reinterpret_cast<const float4*>(&As[kk][tm]);
            const float4 b = *reinterpret_cast<const float4*>(&Bs[kk][tn]);
            const float av_[4] = {a.x, a.y, a.z, a.w};
            const float bv_[4] = {b.x, b.y, b.z, b.w};
#pragma unroll
            for (int i = 0; i < 4; i++)
#pragma unroll
                for (int j = 0; j < 4; j++)
                    acc[i][j] += av_[i] * bv_[j];
        }
        __syncthreads();
    }
#pragma unroll
    for (int i = 0; i < 4; i++)
#pragma unroll
        for (int j = 0; j < 4; j++)
            Wc[(n0 + tm + i) * HID + k0 + tn + j] = acc[i][j];
}

__global__ __launch_bounds__(256) void prep_biasc(
    const float* __restrict__ w_ih, const float* __restrict__ fc_b,
    const float* __restrict__ b_ih, float* __restrict__ biasC)
{
    const int n = blockIdx.x * 256 + threadIdx.x;
    if (n >= 3 * HID) return;
    float s = b_ih[n];
    for (int o = 0; o < IND; ++o) s += w_ih[n * IND + o] * fc_b[o];
    biasC[n] = s;
}

// --------------------------------------------------------------------------
// Prep 2: build interleaved split gate weights (W1 for t>=1, W0 for t=0).
// --------------------------------------------------------------------------
__global__ __launch_bounds__(256) void prep_gatesW(
    const float* __restrict__ Wc, const float* __restrict__ w_hh,
    __nv_bfloat16* __restrict__ W1, __nv_bfloat16* __restrict__ W0)
{
    const int idx = blockIdx.x * 256 + threadIdx.x;     // over NGATE * HID
    if (idx >= NGATE * HID) return;
    const int n = idx / HID;
    const int k = idx - n * HID;
    const int g = n & 3;            // 0=r,1=z,2=i_n,3=h_n
    const int u = n >> 2;
    float w1, w0;
    if (g == 0)      { w0 = w_hh[u * HID + k];               w1 = w0 + Wc[u * HID + k]; }
    else if (g == 1) { w0 = w_hh[(HID + u) * HID + k];       w1 = w0 + Wc[(HID + u) * HID + k]; }
    else if (g == 2) { w0 = 0.0f;                            w1 = Wc[(2 * HID + u) * HID + k]; }
    else             { w0 = w_hh[(2 * HID + u) * HID + k];   w1 = w0; }

    __nv_bfloat16 hi = __float2bfloat16_rn(w1);
    __nv_bfloat16 lo = __float2bfloat16_rn(w1 - __bfloat162float(hi));
    W1[(size_t)n * KEXT + k]           = hi;
    W1[(size_t)n * KEXT + HID + k]     = lo;
    W1[(size_t)n * KEXT + 2 * HID + k] = hi;
    hi = __float2bfloat16_rn(w0);
    lo = __float2bfloat16_rn(w0 - __bfloat162float(hi));
    W0[(size_t)n * KEXT + k]           = hi;
    W0[(size_t)n * KEXT + HID + k]     = lo;
    W0[(size_t)n * KEXT + 2 * HID + k] = hi;
}

__global__ __launch_bounds__(256) void prep_gbias(
    const float* __restrict__ biasC, const float* __restrict__ b_ih,
    const float* __restrict__ b_hh,
    float* __restrict__ bias1, float* __restrict__ bias0)
{
    const int n = blockIdx.x * 256 + threadIdx.x;
    if (n >= NGATE) return;
    const int g = n & 3, u = n >> 2;
    float b1, b0;
    if (g == 0)      { b1 = biasC[u] + b_hh[u];                     b0 = b_ih[u] + b_hh[u]; }
    else if (g == 1) { b1 = biasC[HID + u] + b_hh[HID + u];         b0 = b_ih[HID + u] + b_hh[HID + u]; }
    else if (g == 2) { b1 = biasC[2 * HID + u];                     b0 = b_ih[2 * HID + u]; }
    else             { b1 = b_hh[2 * HID + u];                      b0 = b1; }
    bias1[n] = b1;
    bias0[n] = b0;
}

__global__ __launch_bounds__(256) void prep_fcw(
    const float* __restrict__ fc_w, __nv_bfloat16* __restrict__ fcW)
{
    const int idx = blockIdx.x * 256 + threadIdx.x;     // over OUTD * HID
    if (idx >= OUTD * HID) return;
    const int n = idx / HID;
    const int k = idx - n * HID;
    const float w = fc_w[idx];
    const __nv_bfloat16 hi = __float2bfloat16_rn(w);
    const __nv_bfloat16 lo = __float2bfloat16_rn(w - __bfloat162float(hi));
    fcW[(size_t)n * KEXT + k]           = hi;
    fcW[(size_t)n * KEXT + HID + k]     = lo;
    fcW[(size_t)n * KEXT + 2 * HID + k] = hi;
}

__global__ __launch_bounds__(256) void prep_act0(
    const float* __restrict__ hidden, __nv_bfloat16* __restrict__ act)
{
    const int idx = blockIdx.x * 256 + threadIdx.x;     // over BATCH * HID
    if (idx >= BATCH * HID) return;
    const int m = idx / HID;
    const int c = idx - m * HID;
    const float h = hidden[idx];
    const __nv_bfloat16 hi = __float2bfloat16_rn(h);
    const __nv_bfloat16 lo = __float2bfloat16_rn(h - __bfloat162float(hi));
    act[(size_t)m * KEXT + c]           = hi;
    act[(size_t)m * KEXT + HID + c]     = hi;
    act[(size_t)m * KEXT + 2 * HID + c] = lo;
}

// --------------------------------------------------------------------------
// Gates GEMM (warp MMA) + fused GRU epilogue
//   D[m,n] = act[m,:] . W[n,:]  (M=2048, N=2048, K=1536 bf16, fp32 acc)
//   CTA 128x128, BK=32, cp.async double buffer, 8 warps (2m x 4n), warp 64x32.
// --------------------------------------------------------------------------
#define GP     80                         // smem row pitch bytes (40 bf16)
#define G_AB   (128 * GP)                 // one A/B buffer: 10240 B
#define G_PIPE (4 * G_AB)                 // A0 A1 B0 B1 = 40960
#define G_SLABPITCH 34
#define G_SLAB (64 * G_SLABPITCH * 4)     // 8704 B per warp
#define G_SMEM (G_PIPE + 8 * G_SLAB)      // 110592 B
#define G_NIT  (KEXT / 32)                // 48

__global__ __launch_bounds__(256, 2)
void gates_kernel(const __nv_bfloat16* __restrict__ act,
                  const __nv_bfloat16* __restrict__ W,
                  const float* __restrict__ bias,
                  __nv_bfloat16* __restrict__ act_next)
{
    extern __shared__ char smem[];
    const uint32_t sb = smem_u32(smem);
    const int tid  = threadIdx.x;
    const int wid  = tid >> 5;
    const int lane = tid & 31;
    const int m0 = blockIdx.x * 128;
    const int n0 = blockIdx.y * 128;
    const int u0 = blockIdx.y * 32;

    const uint32_t sA0 = sb;
    const uint32_t sB0 = sb + 2 * G_AB;

    const int r0c = tid >> 2,         ch0 = (tid & 3);
    const int r1c = (tid + 256) >> 2, ch1 = ((tid + 256) & 3);

    const uint32_t aRow  = (uint32_t)(lane & 15);
    const uint32_t aKoff = (uint32_t)((lane >> 4) * 16);
    const uint32_t bRow  = (uint32_t)((lane & 7) + ((lane >> 4) << 3));
    const uint32_t bKoff = (uint32_t)(((lane >> 3) & 1) * 16);

    const int mW = (wid >> 2) * 64;
    const int nW = (wid & 3) * 32;

    float acc[4][4][4];
#pragma unroll
    for (int i = 0; i < 4; i++)
#pragma unroll
        for (int j = 0; j < 4; j++)
#pragma unroll
            for (int q = 0; q < 4; q++) acc[i][j][q] = 0.0f;

    {
        const int kb = 0;
        CP16(sA0 + r0c * GP + ch0 * 16, act + (size_t)(m0 + r0c) * KEXT + kb + ch0 * 8);
        CP16(sA0 + r1c * GP + ch1 * 16, act + (size_t)(m0 + r1c) * KEXT + kb + ch1 * 8);
        CP16(sB0 + r0c * GP + ch0 * 16, W   + (size_t)(n0 + r0c) * KEXT + kb + ch0 * 8);
        CP16(sB0 + r1c * GP + ch1 * 16, W   + (size_t)(n0 + r1c) * KEXT + kb + ch1 * 8);
        CP_COMMIT();
    }

    for (int kc = 0; kc < G_NIT; ++kc) {
        if (kc + 1 < G_NIT) {
            const int nb = (kc + 1) & 1;
            const uint32_t dA = sA0 + nb * G_AB;
            const uint32_t dB = sB0 + nb * G_AB;
            const int kb = (kc + 1) * 32;
            CP16(dA + r0c * GP + ch0 * 16, act + (size_t)(m0 + r0c) * KEXT + kb + ch0 * 8);
            CP16(dA + r1c * GP + ch1 * 16, act + (size_t)(m0 + r1c) * KEXT + kb + ch1 * 8);
            CP16(dB + r0c * GP + ch0 * 16, W   + (size_t)(n0 + r0c) * KEXT + kb + ch0 * 8);
            CP16(dB + r1c * GP + ch1 * 16, W   + (size_t)(n0 + r1c) * KEXT + kb + ch1 * 8);
            CP_COMMIT();
            CP_WAIT1();
        } else {
            CP_WAIT0();
        }
        __syncthreads();

        const int buf = kc & 1;
        const uint32_t cA = sA0 + buf * G_AB;
        const uint32_t cB = sB0 + buf * G_AB;
#pragma unroll
        for (int ks = 0; ks < 2; ++ks) {
            uint32_t a[4][4], b[2][4];
#pragma unroll
            for (int mt = 0; mt < 4; ++mt)
                ldsm_x4(a[mt], cA + (mW + mt * 16 + aRow) * GP + aKoff + ks * 32);
#pragma unroll
            for (int bj = 0; bj < 2; ++bj)
                ldsm_x4(b[bj], cB + (nW + bj * 16 + bRow) * GP + bKoff + ks * 32);
#pragma unroll
            for (int mt = 0; mt < 4; ++mt)
#pragma unroll
                for (int nt = 0; nt < 4; ++nt)
                    mma16816(acc[mt][nt], a[mt], &b[nt >> 1][(nt & 1) * 2]);
        }
        __syncthreads();
    }

    // ---- epilogue: per-warp slab -> GRU -> act_next ----
    float* slab = reinterpret_cast<float*>(smem + G_PIPE + wid * G_SLAB);
    const int gg = lane >> 2;
    const int t2 = (lane & 3) * 2;
#pragma unroll
    for (int mt = 0; mt < 4; ++mt)
#pragma unroll
        for (int nt = 0; nt < 4; ++nt) {
            const int r = mt * 16 + gg;
            const int c = nt * 8 + t2;
            slab[r * G_SLABPITCH + c]           = acc[mt][nt][0];
            slab[r * G_SLABPITCH + c + 1]       = acc[mt][nt][1];
            slab[(r + 8) * G_SLABPITCH + c]     = acc[mt][nt][2];
            slab[(r + 8) * G_SLABPITCH + c + 1] = acc[mt][nt][3];
        }
    __syncwarp();

#pragma unroll 4
    for (int i = 0; i < 16; ++i) {
        const int e   = lane + 32 * i;          // 0..511
        const int row = e >> 3;                 // 0..63
        const int uu  = e & 7;                  // unit within warp slab
        const int nb  = n0 + nW + uu * 4;
        const float pr = slab[row * G_SLABPITCH + uu * 4 + 0] + __ldg(&bias[nb + 0]);
        const float pz = slab[row * G_SLABPITCH + uu * 4 + 1] + __ldg(&bias[nb + 1]);
        const float pi = slab[row * G_SLABPITCH + uu * 4 + 2] + __ldg(&bias[nb + 2]);
        const float ph = slab[row * G_SLABPITCH + uu * 4 + 3] + __ldg(&bias[nb + 3]);
        const int m = m0 + mW + row;
        const size_t base = (size_t)m * KEXT;
        const int ug = u0 + (nW >> 2) + uu;
        const float ho = __bfloat162float(act[base + ug]) +
                         __bfloat162float(act[base + 2 * HID + ug]);
        const float r  = sigmoidf_(pr);
        const float z  = sigmoidf_(pz);
        const float nn = tanhf(pi + r * ph);
        const float hn = (1.0f - z) * nn + z * ho;
        const __nv_bfloat16 hi = __float2bfloat16_rn(hn);
        const __nv_bfloat16 lo = __float2bfloat16_rn(hn - __bfloat162float(hi));
        act_next[base + ug]           = hi;
        act_next[base + HID + ug]     = hi;
        act_next[base + 2 * HID + ug] = lo;
    }
}

// --------------------------------------------------------------------------
// Batched final fc GEMM:  Y = Hist[1..SEQ] @ fc_w^T + fc_b
//   M = SEQ*BATCH = 262144, N = 128, K = 1536 (split).
//   CTA 128x128, 8 warps (2m x 4n), same pipeline as gates.
//   Row m -> t = m>>11, b = m&2047 ; out[b][SEQ-1-t][:].
// --------------------------------------------------------------------------
__global__ __launch_bounds__(256, 2)
void fc_final(const __nv_bfloat16* __restrict__ A,   // hist + BATCH*KEXT
              const __nv_bfloat16* __restrict__ fcW,
              const float* __restrict__ fc_b,
              float* __restrict__ out)
{
    extern __shared__ char smem[];
    const uint32_t sb = smem_u32(smem);
    const int tid  = threadIdx.x;
    const int wid  = tid >> 5;
    const int lane = tid & 31;
    const size_t m0 = (size_t)blockIdx.x * 128;

    const uint32_t sA0 = sb;
    const uint32_t sB0 = sb + 2 * G_AB;

    const int r0c = tid >> 2,         ch0 = (tid & 3);
    const int r1c = (tid + 256) >> 2, ch1 = ((tid + 256) & 3);

    const uint32_t aRow  = (uint32_t)(lane & 15);
    const uint32_t aKoff = (uint32_t)((lane >> 4) * 16);
    const uint32_t bRow  = (uint32_t)((lane & 7) + ((lane >> 4) << 3));
    const uint32_t bKoff = (uint32_t)(((lane >> 3) & 1) * 16);

    const int mW = (wid >> 2) * 64;
    const int nW = (wid & 3) * 32;

    float acc[4][4][4];
#pragma unroll
    for (int i = 0; i < 4; i++)
#pragma unroll
        for (int j = 0; j < 4; j++)
#pragma unroll
            for (int q = 0; q < 4; q++) acc[i][j][q] = 0.0f;

    {
        const int kb = 0;
        CP16(sA0 + r0c * GP + ch0 * 16, A   + (m0 + r0c) * KEXT + kb + ch0 * 8);
        CP16(sA0 + r1c * GP + ch1 * 16, A   + (m0 + r1c) * KEXT + kb + ch1 * 8);
        CP16(sB0 + r0c * GP + ch0 * 16, fcW + (size_t)r0c * KEXT + kb + ch0 * 8);
        CP16(sB0 + r1c * GP + ch1 * 16, fcW + (size_t)r1c * KEXT + kb + ch1 * 8);
        CP_COMMIT();
    }

    for (int kc = 0; kc < G_NIT; ++kc) {
        if (kc + 1 < G_NIT) {
            const int nb = (kc + 1) & 1;
            const uint32_t dA = sA0 + nb * G_AB;
            const uint32_t dB = sB0 + nb * G_AB;
            const int kb = (kc + 1) * 32;
            CP16(dA + r0c * GP + ch0 * 16, A   + (m0 + r0c) * KEXT + kb + ch0 * 8);
            CP16(dA + r1c * GP + ch1 * 16, A   + (m0 + r1c) * KEXT + kb + ch1 * 8);
            CP16(dB + r0c * GP + ch0 * 16, fcW + (size_t)r0c * KEXT + kb + ch0 * 8);
            CP16(dB + r1c * GP + ch1 * 16, fcW + (size_t)r1c * KEXT + kb + ch1 * 8);
            CP_COMMIT();
            CP_WAIT1();
        } else {
            CP_WAIT0();
        }
        __syncthreads();

        const int buf = kc & 1;
        const uint32_t cA = sA0 + buf * G_AB;
        const uint32_t cB = sB0 + buf * G_AB;
#pragma unroll
        for (int ks = 0; ks < 2; ++ks) {
            uint32_t a[4][4], b[2][4];
#pragma unroll
            for (int mt = 0; mt < 4; ++mt)
                ldsm_x4(a[mt], cA + (mW + mt * 16 + aRow) * GP + aKoff + ks * 32);
#pragma unroll
            for (int bj = 0; bj < 2; ++bj)
                ldsm_x4(b[bj], cB + (nW + bj * 16 + bRow) * GP + bKoff + ks * 32);
#pragma unroll
            for (int mt = 0; mt < 4; ++mt)
#pragma unroll
                for (int nt = 0; nt < 4; ++nt)
                    mma16816(acc[mt][nt], a[mt], &b[nt >> 1][(nt & 1) * 2]);
        }
        __syncthreads();
    }

    // epilogue: slab -> +bias -> out (seq-reversed row mapping)
    float* slab = reinterpret_cast<float*>(smem + G_PIPE + wid * G_SLAB);
    const int gg = lane >> 2;
    const int t2 = (lane & 3) * 2;
#pragma unroll
    for (int mt = 0; mt < 4; ++mt)
#pragma unroll
        for (int nt = 0; nt < 4; ++nt) {
            const int r = mt * 16 + gg;
            const int c = nt * 8 + t2;
            slab[r * G_SLABPITCH + c]           = acc[mt][nt][0];
            slab[r * G_SLABPITCH + c + 1]       = acc[mt][nt][1];
            slab[(r + 8) * G_SLABPITCH + c]     = acc[mt][nt][2];
            slab[(r + 8) * G_SLABPITCH + c + 1] = acc[mt][nt][3];
        }
    __syncwarp();

#pragma unroll 4
    for (int i = 0; i < 64; ++i) {
        const int e   = lane + 32 * i;          // 0..2047
        const int row = e >> 5;                 // 0..63
        const int c   = e & 31;
        const int n   = nW + c;
        const float y = slab[row * G_SLABPITCH + c] + __ldg(&fc_b[n]);
        const size_t m = m0 + mW + row;
        const int t  = (int)(m >> 11);
        const int bb = (int)(m & 2047);
        out[(size_t)bb * SEQ * OUTD + (size_t)(SEQ - 1 - t) * OUTD + n] = y;
    }
}

// --------------------------------------------------------------------------
// Launch
// --------------------------------------------------------------------------
extern "C" void kernel_launch(void* const* d_in, const int* in_sizes, int n_in,
                              void* d_out, int out_size)
{
    const float* hidden = (const float*)d_in[0];
    const float* w_ih   = (const float*)d_in[1];
    const float* w_hh   = (const float*)d_in[2];
    const float* b_ih   = (const float*)d_in[3];
    const float* b_hh   = (const float*)d_in[4];
    const float* fc_w   = (const float*)d_in[5];
    const float* fc_b   = (const float*)d_in[6];
    float* out = (float*)d_out;

    __nv_bfloat16 *pW1, *pW0, *pfcW, *phist;
    float *pWc, *pbiasC, *pbias1, *pbias0;
    cudaGetSymbolAddress((void**)&pW1,    g_W1);
    cudaGetSymbolAddress((void**)&pW0,    g_W0);
    cudaGetSymbolAddress((void**)&pfcW,   g_fcW);
    cudaGetSymbolAddress((void**)&phist,  g_hist);
    cudaGetSymbolAddress((void**)&pWc,    g_Wc);
    cudaGetSymbolAddress((void**)&pbiasC, g_biasC);
    cudaGetSymbolAddress((void**)&pbias1, g_bias1);
    cudaGetSymbolAddress((void**)&pbias0, g_bias0);

    cudaFuncSetAttribute(gates_kernel, cudaFuncAttributeMaxDynamicSharedMemorySize, G_SMEM);
    cudaFuncSetAttribute(fc_final,     cudaFuncAttributeMaxDynamicSharedMemorySize, G_SMEM);

    // ---- prep ----
    prep_wc<<<dim3(HID / 64, 3 * HID / 64), 256>>>(w_ih, fc_w, pWc);
    prep_biasc<<<(3 * HID + 255) / 256, 256>>>(w_ih, fc_b, b_ih, pbiasC);
    prep_gatesW<<<(NGATE * HID + 255) / 256, 256>>>(pWc, w_hh, pW1, pW0);
    prep_gbias<<<(NGATE + 255) / 256, 256>>>(pbiasC, b_ih, b_hh, pbias1, pbias0);
    prep_fcw<<<(OUTD * HID + 255) / 256, 256>>>(fc_w, pfcW);
    prep_act0<<<(BATCH * HID + 255) / 256, 256>>>(hidden, phist);

    // ---- recurrence: gates only ----
    const dim3 gates_grid(BATCH / 128, NGATE / 128);   // (16, 16)
    const size_t slice = (size_t)BATCH * KEXT;
    for (int t = 0; t < SEQ; t++) {
        gates_kernel<<<gates_grid, 256, G_SMEM>>>(
            phist + (size_t)t * slice,
            t == 0 ? pW0 : pW1,
            t == 0 ? pbias0 : pbias1,
            phist + (size_t)(t + 1) * slice);
    }

    // ---- batched output fc over all steps ----
    fc_final<<<SEQ * BATCH / 128, 256, G_SMEM>>>(phist + slice, pfcW, fc_b, out);
}